// round 10
// baseline (speedup 1.0000x reference)
#include <cuda_runtime.h>

// Problem dims (fixed by the reference)
#define BB  2
#define SS  2048
#define DD  1024
#define HH  16
#define HD  64
#define MM  (BB*SS)          // 4096 rows for the projections

// ---------------------------------------------------------------------------
// Scratch (device globals -- no cudaMalloc allowed)
// ---------------------------------------------------------------------------
__device__ float g_Q[BB*HH*SS*HD];     // [B,H,S,Hd], pre-scaled by 1/sqrt(Hd)
__device__ float g_K[BB*HH*SS*HD];     // [B,H,S,Hd]
__device__ float g_V[BB*HH*SS*HD];     // [B,H,S,Hd]
__device__ float g_attn[BB*SS*DD];     // [B,S,H*Hd]  (ready for out-proj)
__device__ float g_vsum[BB*HH*HD];     // per-(b,h) sum over k of V

// ---------------------------------------------------------------------------
// SGEMM: Y = (X @ W^T + bias) * scale
//   X: [M,K] row-major, W: [N,K] row-major (torch Linear weight)
// MODE 0: Y row-major [M,N]
// MODE 1: Y scattered to [B,H,S,Hd]  (m=b*S+s, n=h*64+hd)
// Tiles: 128x128x16, 256 threads, 8x8 per thread.
// ---------------------------------------------------------------------------
template<int MODE>
__global__ __launch_bounds__(256)
void sgemm_xwT(const float* __restrict__ X, const float* __restrict__ W,
               const float* __restrict__ bias, float* __restrict__ Y,
               int M, int N, int K, float scale)
{
    __shared__ float As[16][128];
    __shared__ float Bs[16][128];

    const int tid = threadIdx.x;
    const int tx  = tid & 15;        // -> n
    const int ty  = tid >> 4;        // -> m
    const int m0  = blockIdx.y * 128;
    const int n0  = blockIdx.x * 128;

    float acc[8][8];
#pragma unroll
    for (int i = 0; i < 8; i++)
#pragma unroll
        for (int j = 0; j < 8; j++) acc[i][j] = 0.f;

    for (int k0 = 0; k0 < K; k0 += 16) {
        __syncthreads();
        // cooperative load: 128x16 of X and W, as float4
#pragma unroll
        for (int r = 0; r < 2; r++) {
            int idx = tid + r * 256;          // 0..511
            int mm  = idx >> 2;               // 0..127
            int kq  = idx & 3;                // 0..3 (quad of 4 K-values)
            float4 va = *reinterpret_cast<const float4*>(
                &X[(size_t)(m0 + mm) * K + k0 + kq * 4]);
            As[kq*4+0][mm] = va.x; As[kq*4+1][mm] = va.y;
            As[kq*4+2][mm] = va.z; As[kq*4+3][mm] = va.w;
            float4 vb = *reinterpret_cast<const float4*>(
                &W[(size_t)(n0 + mm) * K + k0 + kq * 4]);
            Bs[kq*4+0][mm] = vb.x; Bs[kq*4+1][mm] = vb.y;
            Bs[kq*4+2][mm] = vb.z; Bs[kq*4+3][mm] = vb.w;
        }
        __syncthreads();

#pragma unroll
        for (int kk = 0; kk < 16; kk++) {
            float a[8], b[8];
#pragma unroll
            for (int i = 0; i < 8; i += 4) {
                float4 t = *reinterpret_cast<const float4*>(&As[kk][ty*8 + i]);
                a[i] = t.x; a[i+1] = t.y; a[i+2] = t.z; a[i+3] = t.w;
            }
#pragma unroll
            for (int j = 0; j < 8; j += 4) {
                float4 t = *reinterpret_cast<const float4*>(&Bs[kk][tx*8 + j]);
                b[j] = t.x; b[j+1] = t.y; b[j+2] = t.z; b[j+3] = t.w;
            }
#pragma unroll
            for (int i = 0; i < 8; i++)
#pragma unroll
                for (int j = 0; j < 8; j++)
                    acc[i][j] += a[i] * b[j];
        }
    }

    // epilogue
    const int nb = n0 + tx * 8;
    float bi[8];
#pragma unroll
    for (int j = 0; j < 8; j++) bi[j] = bias[nb + j];

#pragma unroll
    for (int i = 0; i < 8; i++) {
        int m = m0 + ty * 8 + i;
        float out[8];
#pragma unroll
        for (int j = 0; j < 8; j++) out[j] = (acc[i][j] + bi[j]) * scale;

        float* dst;
        if (MODE == 0) {
            dst = &Y[(size_t)m * N + nb];
        } else {
            int b = m / SS, s = m - b * SS;
            int h = nb >> 6, hdo = nb & 63;   // nb%64..+7 never crosses a head
            dst = &Y[(((size_t)(b * HH + h)) * SS + s) * HD + hdo];
        }
        *reinterpret_cast<float4*>(dst)     = make_float4(out[0], out[1], out[2], out[3]);
        *reinterpret_cast<float4*>(dst + 4) = make_float4(out[4], out[5], out[6], out[7]);
    }
}

// ---------------------------------------------------------------------------
// Per-(b,h) column sums of V -> g_vsum
// ---------------------------------------------------------------------------
__global__ void vsum_kernel(const float* __restrict__ V, float* __restrict__ vs)
{
    int bh = blockIdx.x;
    int j  = threadIdx.x;                  // 0..63
    const float* base = &V[(size_t)bh * SS * HD + j];
    float s = 0.f;
    for (int k = 0; k < SS; k++) s += base[(size_t)k * HD];
    vs[bh * HD + j] = s;
}

// ---------------------------------------------------------------------------
// Streaming evidence-attention (flash-style, no max needed).
// Q already carries the 1/sqrt(Hd) scale.
// grid: (S/128, B*H), 128 threads; each thread owns one q row.
// ---------------------------------------------------------------------------
__global__ __launch_bounds__(128)
void attn_kernel(const float* __restrict__ Q, const float* __restrict__ K,
                 const float* __restrict__ V, const float* __restrict__ vsum,
                 const float* __restrict__ es_p, const float* __restrict__ eb_p,
                 float* __restrict__ attn_out, float* __restrict__ unc_out)
{
    const int KT = 32;
    __shared__ float Ks[KT][HD];
    __shared__ float Vs[KT][HD];

    const int tid = threadIdx.x;
    const int bh  = blockIdx.y;
    const int q   = blockIdx.x * 128 + tid;

    // Q row into registers (16 float4 = 64 floats)
    float4 qr[16];
    {
        const float4* qp = reinterpret_cast<const float4*>(
            &Q[((size_t)bh * SS + q) * HD]);
#pragma unroll
        for (int i = 0; i < 16; i++) qr[i] = qp[i];
    }

    float4 acc[16];
#pragma unroll
    for (int i = 0; i < 16; i++) acc[i] = make_float4(0.f, 0.f, 0.f, 0.f);
    float E = 0.f;

    const float* kbase = &K[(size_t)bh * SS * HD];
    const float* vbase = &V[(size_t)bh * SS * HD];

    for (int k0 = 0; k0 < SS; k0 += KT) {
        __syncthreads();
        // load K/V tile: KT*64 floats each = 512 float4 each, 128 threads
#pragma unroll
        for (int r = 0; r < 4; r++) {
            int idx  = tid + r * 128;        // 0..511
            int row  = idx >> 4;             // 0..31
            int quad = idx & 15;             // 0..15
            *reinterpret_cast<float4*>(&Ks[row][quad * 4]) =
                *reinterpret_cast<const float4*>(&kbase[(size_t)(k0 + row) * HD + quad * 4]);
            *reinterpret_cast<float4*>(&Vs[row][quad * 4]) =
                *reinterpret_cast<const float4*>(&vbase[(size_t)(k0 + row) * HD + quad * 4]);
        }
        __syncthreads();

#pragma unroll 4
        for (int kk = 0; kk < KT; kk++) {
            float s = 0.f;
#pragma unroll
            for (int i = 0; i < 16; i++) {
                float4 kv = *reinterpret_cast<const float4*>(&Ks[kk][i * 4]);
                s += qr[i].x * kv.x + qr[i].y * kv.y + qr[i].z * kv.z + qr[i].w * kv.w;
            }
            float p = __expf(s);
            E += p;
#pragma unroll
            for (int i = 0; i < 16; i++) {
                float4 vv = *reinterpret_cast<const float4*>(&Vs[kk][i * 4]);
                acc[i].x += p * vv.x; acc[i].y += p * vv.y;
                acc[i].z += p * vv.z; acc[i].w += p * vv.w;
            }
        }
    }

    const float es   = *es_p;
    const float c    = 1.0f + *eb_p;
    const float den  = es * E + c * (float)SS;
    const float inv  = 1.0f / den;

    const int b = bh / HH, h = bh % HH;
    const float4* vsv = reinterpret_cast<const float4*>(&vsum[bh * HD]);
    float4* dst = reinterpret_cast<float4*>(
        &attn_out[(((size_t)b * SS + q) * HH + h) * HD]);
#pragma unroll
    for (int i = 0; i < 16; i++) {
        float4 vs4 = vsv[i];
        float4 o;
        o.x = (es * acc[i].x + c * vs4.x) * inv;
        o.y = (es * acc[i].y + c * vs4.y) * inv;
        o.z = (es * acc[i].z + c * vs4.z) * inv;
        o.w = (es * acc[i].w + c * vs4.w) * inv;
        dst[i] = o;
    }
    unc_out[(size_t)bh * SS + q] = (float)SS * inv;
}

// ---------------------------------------------------------------------------
// kernel_launch
// inputs: x, q_w, q_b, k_w, k_b, v_w, v_b, out_w, out_b, evidence_scale, evidence_bias
// output: concat(output[B,S,D], uncertainty[B,H,S])  (fp32)
// ---------------------------------------------------------------------------
extern "C" void kernel_launch(void* const* d_in, const int* in_sizes, int n_in,
                              void* d_out, int out_size)
{
    const float* x     = (const float*)d_in[0];
    const float* q_w   = (const float*)d_in[1];
    const float* q_b   = (const float*)d_in[2];
    const float* k_w   = (const float*)d_in[3];
    const float* k_b   = (const float*)d_in[4];
    const float* v_w   = (const float*)d_in[5];
    const float* v_b   = (const float*)d_in[6];
    const float* out_w = (const float*)d_in[7];
    const float* out_b = (const float*)d_in[8];
    const float* es    = (const float*)d_in[9];
    const float* eb    = (const float*)d_in[10];
    float* out = (float*)d_out;

    float *Qb, *Kb, *Vb, *Ab, *VS;
    cudaGetSymbolAddress((void**)&Qb, g_Q);
    cudaGetSymbolAddress((void**)&Kb, g_K);
    cudaGetSymbolAddress((void**)&Vb, g_V);
    cudaGetSymbolAddress((void**)&Ab, g_attn);
    cudaGetSymbolAddress((void**)&VS, g_vsum);

    const float inv_sqrt_hd = 0.125f;   // 1/sqrt(64), folded into Q

    dim3 gemm_grid(DD / 128, MM / 128); // (8, 32)
    sgemm_xwT<1><<<gemm_grid, 256>>>(x, q_w, q_b, Qb, MM, DD, DD, inv_sqrt_hd);
    sgemm_xwT<1><<<gemm_grid, 256>>>(x, k_w, k_b, Kb, MM, DD, DD, 1.0f);
    sgemm_xwT<1><<<gemm_grid, 256>>>(x, v_w, v_b, Vb, MM, DD, DD, 1.0f);

    vsum_kernel<<<BB * HH, HD>>>(Vb, VS);

    dim3 attn_grid(SS / 128, BB * HH);  // (16, 32)
    attn_kernel<<<attn_grid, 128>>>(Qb, Kb, Vb, VS, es, eb,
                                    Ab, out + (size_t)BB * SS * DD);

    sgemm_xwT<0><<<gemm_grid, 256>>>(Ab, out_w, out_b, out, MM, DD, DD, 1.0f);
}

// round 12
// speedup vs baseline: 1.0688x; 1.0688x over previous
#include <cuda_runtime.h>
#include <cstdint>

// Problem dims (fixed by the reference)
#define BB  2
#define SS  2048
#define DD  1024
#define HH  16
#define HD  64
#define MM  (BB*SS)          // 4096 rows for the projections

// ---------------------------------------------------------------------------
// Scratch (device globals -- no cudaMalloc allowed)
// ---------------------------------------------------------------------------
__device__ float g_Q[BB*HH*SS*HD];     // [B,H,S,Hd], pre-scaled by 1/sqrt(Hd)
__device__ float g_K[BB*HH*SS*HD];     // [B,H,S,Hd]
__device__ float g_V[BB*HH*SS*HD];     // [B,H,S,Hd]
__device__ float g_attn[BB*SS*DD];     // [B,S,H*Hd]  (ready for out-proj)
__device__ float g_vsum[BB*HH*HD];     // per-(b,h) sum over k of V

// ---------------------------------------------------------------------------
// Baseline-PTX helpers (sm_80+; NO tcgen05 -- harness targets plain sm_103)
// ---------------------------------------------------------------------------
__device__ __forceinline__ uint32_t smem_u32(const void* p) {
    uint32_t a;
    asm("{ .reg .u64 t; cvta.to.shared.u64 t, %1; cvt.u32.u64 %0, t; }"
        : "=r"(a) : "l"(p));
    return a;
}
__device__ __forceinline__ uint32_t f2tf32(float x) {
    uint32_t u; asm("cvt.rna.tf32.f32 %0, %1;" : "=r"(u) : "f"(x));
    return u;
}
__device__ __forceinline__ void cp_async16(uint32_t dst, const void* src) {
    asm volatile("cp.async.cg.shared.global [%0], [%1], 16;" :: "r"(dst), "l"(src));
}
__device__ __forceinline__ void cp_commit() {
    asm volatile("cp.async.commit_group;");
}
template<int N>
__device__ __forceinline__ void cp_wait() {
    asm volatile("cp.async.wait_group %0;" :: "n"(N));
}

// mma.sync m16n8k8 tf32: D(4xf32) += A(4xtf32) * B(2xtf32)
__device__ __forceinline__ void mma_tf32(float* d, const uint32_t* a, const uint32_t* b) {
    asm volatile(
        "mma.sync.aligned.m16n8k8.row.col.f32.tf32.tf32.f32 "
        "{%0,%1,%2,%3}, {%4,%5,%6,%7}, {%8,%9}, {%0,%1,%2,%3};"
        : "+f"(d[0]), "+f"(d[1]), "+f"(d[2]), "+f"(d[3])
        : "r"(a[0]), "r"(a[1]), "r"(a[2]), "r"(a[3]), "r"(b[0]), "r"(b[1]));
}

// ---------------------------------------------------------------------------
// 3xTF32 HMMA GEMM: Y = (X @ W^T + bias) * scale
//   X: [4096,1024] row-major, W: [1024,1024] row-major (torch Linear weight)
// MODE 0: Y row-major [M,N] ; MODE 1: scatter to [B,H,S,Hd]
// CTA: 256 threads (8 warps), tile 128x128, warp tile 64x32 (2x4 warp grid),
// K-chunk 16, cp.async double buffer, hi/lo tf32 split in registers.
// ---------------------------------------------------------------------------
#define KC      16
#define NCH     (DD / KC)        // 64
#define SPAD    20               // smem row stride in floats (conflict-free frags)

template<int MODE>
__global__ void __launch_bounds__(256, 1)
gemm_tf32(const float* __restrict__ X, const float* __restrict__ W,
          const float* __restrict__ bias, float* __restrict__ Y, float scale)
{
    __shared__ float As[2][128][SPAD];
    __shared__ float Bs[2][128][SPAD];

    const int tid  = threadIdx.x;
    const int wid  = tid >> 5;
    const int lane = tid & 31;
    const int g    = lane >> 2;        // group id 0..7
    const int tig  = lane & 3;         // thread in group 0..3
    const int wm   = wid & 1;          // warp m index (0..1)  -> 64 rows
    const int wn   = wid >> 1;         // warp n index (0..3)  -> 32 cols
    const int m0   = blockIdx.y * 128;
    const int n0   = blockIdx.x * 128;

    // per-thread load coords: 2 float4 for A, 2 for B per chunk
    const int l_row0 = tid >> 1;             // 0..127  (idx = tid)
    const int l_q0   = (tid & 1) * 2;        // quad 0 or 2
    // second element: idx = tid + 256 -> row same set, q +1
    // simpler: idx r*256+tid: row=(idx>>2), q=idx&3
    float acc[4][4][4];
#pragma unroll
    for (int i = 0; i < 4; i++)
#pragma unroll
        for (int j = 0; j < 4; j++)
#pragma unroll
            for (int k = 0; k < 4; k++) acc[i][j][k] = 0.f;

    // ---- chunk loader (cp.async) ----
    auto load_chunk = [&](int c, int buf) {
#pragma unroll
        for (int r = 0; r < 2; r++) {
            const int idx = tid + r * 256;   // 0..511
            const int row = idx >> 2;        // 0..127
            const int q   = idx & 3;         // float4 slot in 16-wide chunk
            cp_async16(smem_u32(&As[buf][row][q * 4]),
                       &X[(size_t)(m0 + row) * DD + c * KC + q * 4]);
            cp_async16(smem_u32(&Bs[buf][row][q * 4]),
                       &W[(size_t)(n0 + row) * DD + c * KC + q * 4]);
        }
        cp_commit();
    };

    load_chunk(0, 0);

    for (int c = 0; c < NCH; c++) {
        const int buf = c & 1;
        __syncthreads();                       // prev compute on !buf done
        if (c + 1 < NCH) { load_chunk(c + 1, buf ^ 1); cp_wait<1>(); }
        else             { cp_wait<0>(); }
        __syncthreads();                       // chunk c visible to all

#pragma unroll
        for (int k8 = 0; k8 < 2; k8++) {
            const int kb = k8 * 8;
            // A fragments: 4 m-tiles, hi/lo
            uint32_t ah[4][4], al[4][4];
#pragma unroll
            for (int mt = 0; mt < 4; mt++) {
                const int r = wm * 64 + mt * 16 + g;
                float x0 = As[buf][r][kb + tig];
                float x1 = As[buf][r + 8][kb + tig];
                float x2 = As[buf][r][kb + tig + 4];
                float x3 = As[buf][r + 8][kb + tig + 4];
                ah[mt][0] = f2tf32(x0); al[mt][0] = f2tf32(x0 - __uint_as_float(ah[mt][0]));
                ah[mt][1] = f2tf32(x1); al[mt][1] = f2tf32(x1 - __uint_as_float(ah[mt][1]));
                ah[mt][2] = f2tf32(x2); al[mt][2] = f2tf32(x2 - __uint_as_float(ah[mt][2]));
                ah[mt][3] = f2tf32(x3); al[mt][3] = f2tf32(x3 - __uint_as_float(ah[mt][3]));
            }
            // B fragments: 4 n-tiles, hi/lo
            uint32_t bh[4][2], bl[4][2];
#pragma unroll
            for (int nt = 0; nt < 4; nt++) {
                const int r = wn * 32 + nt * 8 + g;
                float x0 = Bs[buf][r][kb + tig];
                float x1 = Bs[buf][r][kb + tig + 4];
                bh[nt][0] = f2tf32(x0); bl[nt][0] = f2tf32(x0 - __uint_as_float(bh[nt][0]));
                bh[nt][1] = f2tf32(x1); bl[nt][1] = f2tf32(x1 - __uint_as_float(bh[nt][1]));
            }
#pragma unroll
            for (int mt = 0; mt < 4; mt++)
#pragma unroll
                for (int nt = 0; nt < 4; nt++) {
                    mma_tf32(acc[mt][nt], ah[mt], bl[nt]);   // cross terms first
                    mma_tf32(acc[mt][nt], al[mt], bh[nt]);
                    mma_tf32(acc[mt][nt], ah[mt], bh[nt]);   // big term
                }
        }
    }

    // ---- epilogue ----
#pragma unroll
    for (int mt = 0; mt < 4; mt++) {
#pragma unroll
        for (int nt = 0; nt < 4; nt++) {
            const int col = n0 + wn * 32 + nt * 8 + 2 * tig;
            const float b0v = bias[col], b1v = bias[col + 1];
            const int r1 = m0 + wm * 64 + mt * 16 + g;
            const int r2 = r1 + 8;

            float2 o0, o1;
            o0.x = (acc[mt][nt][0] + b0v) * scale;
            o0.y = (acc[mt][nt][1] + b1v) * scale;
            o1.x = (acc[mt][nt][2] + b0v) * scale;
            o1.y = (acc[mt][nt][3] + b1v) * scale;

            if (MODE == 0) {
                *reinterpret_cast<float2*>(&Y[(size_t)r1 * DD + col]) = o0;
                *reinterpret_cast<float2*>(&Y[(size_t)r2 * DD + col]) = o1;
            } else {
                const int h  = col >> 6;
                const int hd = col & 63;
                {
                    const int b = r1 >> 11, s = r1 & (SS - 1);
                    *reinterpret_cast<float2*>(
                        &Y[(((size_t)(b * HH + h)) * SS + s) * HD + hd]) = o0;
                }
                {
                    const int b = r2 >> 11, s = r2 & (SS - 1);
                    *reinterpret_cast<float2*>(
                        &Y[(((size_t)(b * HH + h)) * SS + s) * HD + hd]) = o1;
                }
            }
        }
    }
}

// ---------------------------------------------------------------------------
// Per-(b,h) column sums of V -> g_vsum  (parallelized over 8 row-chunks)
// ---------------------------------------------------------------------------
__global__ void vsum_kernel(const float* __restrict__ V, float* __restrict__ vs)
{
    __shared__ float red[8][HD];
    const int bh  = blockIdx.x;
    const int col = threadIdx.x & 63;
    const int ch  = threadIdx.x >> 6;          // 0..7
    const float* base = &V[(size_t)bh * SS * HD + (size_t)ch * 256 * HD + col];
    float s = 0.f;
#pragma unroll 8
    for (int k = 0; k < 256; k++) s += base[(size_t)k * HD];
    red[ch][col] = s;
    __syncthreads();
    if (ch == 0) {
        float t = 0.f;
#pragma unroll
        for (int i = 0; i < 8; i++) t += red[i][col];
        vs[bh * HD + col] = t;
    }
}

// ---------------------------------------------------------------------------
// Streaming evidence-attention (flash-style, no max needed).
// Q already carries the 1/sqrt(Hd) scale.
// grid: (S/128, B*H), 128 threads; each thread owns one q row.
// ---------------------------------------------------------------------------
__global__ __launch_bounds__(128)
void attn_kernel(const float* __restrict__ Q, const float* __restrict__ K,
                 const float* __restrict__ V, const float* __restrict__ vsum,
                 const float* __restrict__ es_p, const float* __restrict__ eb_p,
                 float* __restrict__ attn_out, float* __restrict__ unc_out)
{
    const int KT = 32;
    __shared__ float Ks[KT][HD];
    __shared__ float Vs[KT][HD];

    const int tid = threadIdx.x;
    const int bh  = blockIdx.y;
    const int q   = blockIdx.x * 128 + tid;

    float4 qr[16];
    {
        const float4* qp = reinterpret_cast<const float4*>(
            &Q[((size_t)bh * SS + q) * HD]);
#pragma unroll
        for (int i = 0; i < 16; i++) qr[i] = qp[i];
    }

    float4 acc[16];
#pragma unroll
    for (int i = 0; i < 16; i++) acc[i] = make_float4(0.f, 0.f, 0.f, 0.f);
    float E = 0.f;

    const float* kbase = &K[(size_t)bh * SS * HD];
    const float* vbase = &V[(size_t)bh * SS * HD];

    for (int k0 = 0; k0 < SS; k0 += KT) {
        __syncthreads();
#pragma unroll
        for (int r = 0; r < 4; r++) {
            int idx  = tid + r * 128;
            int row  = idx >> 4;
            int quad = idx & 15;
            *reinterpret_cast<float4*>(&Ks[row][quad * 4]) =
                *reinterpret_cast<const float4*>(&kbase[(size_t)(k0 + row) * HD + quad * 4]);
            *reinterpret_cast<float4*>(&Vs[row][quad * 4]) =
                *reinterpret_cast<const float4*>(&vbase[(size_t)(k0 + row) * HD + quad * 4]);
        }
        __syncthreads();

#pragma unroll 4
        for (int kk = 0; kk < KT; kk++) {
            float s = 0.f;
#pragma unroll
            for (int i = 0; i < 16; i++) {
                float4 kv = *reinterpret_cast<const float4*>(&Ks[kk][i * 4]);
                s += qr[i].x * kv.x + qr[i].y * kv.y + qr[i].z * kv.z + qr[i].w * kv.w;
            }
            float p = __expf(s);
            E += p;
#pragma unroll
            for (int i = 0; i < 16; i++) {
                float4 vv = *reinterpret_cast<const float4*>(&Vs[kk][i * 4]);
                acc[i].x += p * vv.x; acc[i].y += p * vv.y;
                acc[i].z += p * vv.z; acc[i].w += p * vv.w;
            }
        }
    }

    const float es  = *es_p;
    const float c   = 1.0f + *eb_p;
    const float den = es * E + c * (float)SS;
    const float inv = 1.0f / den;

    const int b = bh / HH, h = bh % HH;
    const float4* vsv = reinterpret_cast<const float4*>(&vsum[bh * HD]);
    float4* dst = reinterpret_cast<float4*>(
        &attn_out[(((size_t)b * SS + q) * HH + h) * HD]);
#pragma unroll
    for (int i = 0; i < 16; i++) {
        float4 vs4 = vsv[i];
        float4 o;
        o.x = (es * acc[i].x + c * vs4.x) * inv;
        o.y = (es * acc[i].y + c * vs4.y) * inv;
        o.z = (es * acc[i].z + c * vs4.z) * inv;
        o.w = (es * acc[i].w + c * vs4.w) * inv;
        dst[i] = o;
    }
    unc_out[(size_t)bh * SS + q] = (float)SS * inv;
}

// ---------------------------------------------------------------------------
// kernel_launch
// ---------------------------------------------------------------------------
extern "C" void kernel_launch(void* const* d_in, const int* in_sizes, int n_in,
                              void* d_out, int out_size)
{
    const float* x     = (const float*)d_in[0];
    const float* q_w   = (const float*)d_in[1];
    const float* q_b   = (const float*)d_in[2];
    const float* k_w   = (const float*)d_in[3];
    const float* k_b   = (const float*)d_in[4];
    const float* v_w   = (const float*)d_in[5];
    const float* v_b   = (const float*)d_in[6];
    const float* out_w = (const float*)d_in[7];
    const float* out_b = (const float*)d_in[8];
    const float* es    = (const float*)d_in[9];
    const float* eb    = (const float*)d_in[10];
    float* out = (float*)d_out;

    float *Qb, *Kb, *Vb, *Ab, *VS;
    cudaGetSymbolAddress((void**)&Qb, g_Q);
    cudaGetSymbolAddress((void**)&Kb, g_K);
    cudaGetSymbolAddress((void**)&Vb, g_V);
    cudaGetSymbolAddress((void**)&Ab, g_attn);
    cudaGetSymbolAddress((void**)&VS, g_vsum);

    const float inv_sqrt_hd = 0.125f;   // 1/sqrt(64), folded into Q after bias

    dim3 gemm_grid(DD / 128, MM / 128); // (8, 32)
    gemm_tf32<1><<<gemm_grid, 256>>>(x, q_w, q_b, Qb, inv_sqrt_hd);
    gemm_tf32<1><<<gemm_grid, 256>>>(x, k_w, k_b, Kb, 1.0f);
    gemm_tf32<1><<<gemm_grid, 256>>>(x, v_w, v_b, Vb, 1.0f);

    vsum_kernel<<<BB * HH, 512>>>(Vb, VS);

    dim3 attn_grid(SS / 128, BB * HH);  // (16, 32)
    attn_kernel<<<attn_grid, 128>>>(Qb, Kb, Vb, VS, es, eb,
                                    Ab, out + (size_t)BB * SS * DD);

    gemm_tf32<0><<<gemm_grid, 256>>>(Ab, out_w, out_b, out, 1.0f);
}

// round 13
// speedup vs baseline: 1.5137x; 1.4162x over previous
#include <cuda_runtime.h>
#include <cstdint>

// Problem dims (fixed by the reference)
#define BB  2
#define SS  2048
#define DD  1024
#define HH  16
#define HD  64
#define MM  (BB*SS)          // 4096 rows for the projections

// ---------------------------------------------------------------------------
// Scratch (device globals -- no cudaMalloc allowed)
// ---------------------------------------------------------------------------
__device__ float g_Q[BB*HH*SS*HD];     // [B,H,S,Hd], pre-scaled by 1/sqrt(Hd)
__device__ float g_K[BB*HH*SS*HD];     // [B,H,S,Hd]
__device__ float g_V[BB*HH*SS*HD];     // [B,H,S,Hd]
__device__ float g_attn[BB*SS*DD];     // [B,S,H*Hd]  (ready for out-proj)
__device__ float g_vsum[BB*HH*HD];     // per-(b,h) sum over k of V
// tf32 hi/lo pre-split buffers (A side reused: x, then attn; W side per-GEMM)
__device__ float g_Ah[MM*DD], g_Al[MM*DD];
__device__ float g_Wh[DD*DD], g_Wl[DD*DD];

// ---------------------------------------------------------------------------
// Baseline-PTX helpers (sm_80+; harness ptxas target is plain sm_103)
// ---------------------------------------------------------------------------
__device__ __forceinline__ uint32_t smem_u32(const void* p) {
    uint32_t a;
    asm("{ .reg .u64 t; cvta.to.shared.u64 t, %1; cvt.u32.u64 %0, t; }"
        : "=r"(a) : "l"(p));
    return a;
}
__device__ __forceinline__ float f2tf32(float x) {
    uint32_t u; asm("cvt.rna.tf32.f32 %0, %1;" : "=r"(u) : "f"(x));
    return __uint_as_float(u);
}
__device__ __forceinline__ void cp_async16(uint32_t dst, const void* src) {
    asm volatile("cp.async.cg.shared.global [%0], [%1], 16;" :: "r"(dst), "l"(src));
}
__device__ __forceinline__ void cp_commit() {
    asm volatile("cp.async.commit_group;");
}
template<int N>
__device__ __forceinline__ void cp_wait() {
    asm volatile("cp.async.wait_group %0;" :: "n"(N));
}

// mma.sync m16n8k8 tf32: D(4xf32) += A(4xtf32) * B(2xtf32)
__device__ __forceinline__ void mma_tf32(float* d, const uint32_t* a, const uint32_t* b) {
    asm volatile(
        "mma.sync.aligned.m16n8k8.row.col.f32.tf32.tf32.f32 "
        "{%0,%1,%2,%3}, {%4,%5,%6,%7}, {%8,%9}, {%0,%1,%2,%3};"
        : "+f"(d[0]), "+f"(d[1]), "+f"(d[2]), "+f"(d[3])
        : "r"(a[0]), "r"(a[1]), "r"(a[2]), "r"(a[3]), "r"(b[0]), "r"(b[1]));
}

// ---------------------------------------------------------------------------
// One-shot tf32 hi/lo split: hi = tf32(x), lo = tf32(x - hi)
// ---------------------------------------------------------------------------
__global__ void __launch_bounds__(256)
split_kernel(const float* __restrict__ src, float* __restrict__ hi,
             float* __restrict__ lo, int n4)
{
    const int i = blockIdx.x * 256 + threadIdx.x;
    if (i >= n4) return;
    const float4 v = reinterpret_cast<const float4*>(src)[i];
    float4 h, l;
    h.x = f2tf32(v.x); l.x = f2tf32(v.x - h.x);
    h.y = f2tf32(v.y); l.y = f2tf32(v.y - h.y);
    h.z = f2tf32(v.z); l.z = f2tf32(v.z - h.z);
    h.w = f2tf32(v.w); l.w = f2tf32(v.w - h.w);
    reinterpret_cast<float4*>(hi)[i] = h;
    reinterpret_cast<float4*>(lo)[i] = l;
}

// ---------------------------------------------------------------------------
// 3xTF32 HMMA GEMM on PRE-SPLIT operands: Y = (A @ W^T + bias) * scale
//   A = Ah+Al: [4096,1024], W = Wh+Wl: [1024,1024] (torch Linear weight)
// MODE 0: Y row-major [M,N] ; MODE 1: scatter to [B,H,S,Hd]
// CTA 256 threads, tile 128x128, warp tile 64x32 (2x4), K-chunk 16,
// cp.async double buffer. Inner loop: pure LDS + HMMA (no cvt).
// ---------------------------------------------------------------------------
#define KC      16
#define NCH     (DD / KC)        // 64
#define SPAD    20               // smem row stride (conflict-free frag reads)

template<int MODE>
__global__ void __launch_bounds__(256, 1)
gemm_split(const float* __restrict__ Ahg, const float* __restrict__ Alg,
           const float* __restrict__ Whg, const float* __restrict__ Wlg,
           const float* __restrict__ bias, float* __restrict__ Y, float scale)
{
    __shared__ float sAh[2][128][SPAD], sAl[2][128][SPAD];
    __shared__ float sBh[2][128][SPAD], sBl[2][128][SPAD];

    const int tid  = threadIdx.x;
    const int wid  = tid >> 5;
    const int lane = tid & 31;
    const int g    = lane >> 2;        // 0..7
    const int tig  = lane & 3;         // 0..3
    const int wm   = wid & 1;          // 64 rows each
    const int wn   = wid >> 1;         // 32 cols each
    const int m0   = blockIdx.y * 128;
    const int n0   = blockIdx.x * 128;

    float acc[4][4][4];
#pragma unroll
    for (int i = 0; i < 4; i++)
#pragma unroll
        for (int j = 0; j < 4; j++)
#pragma unroll
            for (int k = 0; k < 4; k++) acc[i][j][k] = 0.f;

    auto load_chunk = [&](int c, int buf) {
#pragma unroll
        for (int r = 0; r < 2; r++) {
            const int idx = tid + r * 256;   // 0..511
            const int row = idx >> 2;        // 0..127
            const int q   = idx & 3;         // float4 slot in 16-wide chunk
            const size_t ao = (size_t)(m0 + row) * DD + c * KC + q * 4;
            const size_t bo = (size_t)(n0 + row) * DD + c * KC + q * 4;
            cp_async16(smem_u32(&sAh[buf][row][q * 4]), &Ahg[ao]);
            cp_async16(smem_u32(&sAl[buf][row][q * 4]), &Alg[ao]);
            cp_async16(smem_u32(&sBh[buf][row][q * 4]), &Whg[bo]);
            cp_async16(smem_u32(&sBl[buf][row][q * 4]), &Wlg[bo]);
        }
        cp_commit();
    };

    load_chunk(0, 0);

    for (int c = 0; c < NCH; c++) {
        const int buf = c & 1;
        __syncthreads();                       // prev compute on buf^1 done
        if (c + 1 < NCH) { load_chunk(c + 1, buf ^ 1); cp_wait<1>(); }
        else             { cp_wait<0>(); }
        __syncthreads();                       // chunk c visible

#pragma unroll
        for (int k8 = 0; k8 < 2; k8++) {
            const int kb = k8 * 8;
            uint32_t ah[4][4], al[4][4];
#pragma unroll
            for (int mt = 0; mt < 4; mt++) {
                const int r = wm * 64 + mt * 16 + g;
                ah[mt][0] = __float_as_uint(sAh[buf][r][kb + tig]);
                ah[mt][1] = __float_as_uint(sAh[buf][r + 8][kb + tig]);
                ah[mt][2] = __float_as_uint(sAh[buf][r][kb + tig + 4]);
                ah[mt][3] = __float_as_uint(sAh[buf][r + 8][kb + tig + 4]);
                al[mt][0] = __float_as_uint(sAl[buf][r][kb + tig]);
                al[mt][1] = __float_as_uint(sAl[buf][r + 8][kb + tig]);
                al[mt][2] = __float_as_uint(sAl[buf][r][kb + tig + 4]);
                al[mt][3] = __float_as_uint(sAl[buf][r + 8][kb + tig + 4]);
            }
            uint32_t bh[4][2], bl[4][2];
#pragma unroll
            for (int nt = 0; nt < 4; nt++) {
                const int r = wn * 32 + nt * 8 + g;
                bh[nt][0] = __float_as_uint(sBh[buf][r][kb + tig]);
                bh[nt][1] = __float_as_uint(sBh[buf][r][kb + tig + 4]);
                bl[nt][0] = __float_as_uint(sBl[buf][r][kb + tig]);
                bl[nt][1] = __float_as_uint(sBl[buf][r][kb + tig + 4]);
            }
#pragma unroll
            for (int mt = 0; mt < 4; mt++)
#pragma unroll
                for (int nt = 0; nt < 4; nt++) {
                    mma_tf32(acc[mt][nt], ah[mt], bl[nt]);   // cross terms
                    mma_tf32(acc[mt][nt], al[mt], bh[nt]);
                    mma_tf32(acc[mt][nt], ah[mt], bh[nt]);   // big term
                }
        }
    }

    // ---- epilogue ----
#pragma unroll
    for (int mt = 0; mt < 4; mt++) {
#pragma unroll
        for (int nt = 0; nt < 4; nt++) {
            const int col = n0 + wn * 32 + nt * 8 + 2 * tig;
            const float b0v = bias[col], b1v = bias[col + 1];
            const int r1 = m0 + wm * 64 + mt * 16 + g;
            const int r2 = r1 + 8;

            float2 o0, o1;
            o0.x = (acc[mt][nt][0] + b0v) * scale;
            o0.y = (acc[mt][nt][1] + b1v) * scale;
            o1.x = (acc[mt][nt][2] + b0v) * scale;
            o1.y = (acc[mt][nt][3] + b1v) * scale;

            if (MODE == 0) {
                *reinterpret_cast<float2*>(&Y[(size_t)r1 * DD + col]) = o0;
                *reinterpret_cast<float2*>(&Y[(size_t)r2 * DD + col]) = o1;
            } else {
                const int h  = col >> 6;
                const int hd = col & 63;
                {
                    const int b = r1 >> 11, s = r1 & (SS - 1);
                    *reinterpret_cast<float2*>(
                        &Y[(((size_t)(b * HH + h)) * SS + s) * HD + hd]) = o0;
                }
                {
                    const int b = r2 >> 11, s = r2 & (SS - 1);
                    *reinterpret_cast<float2*>(
                        &Y[(((size_t)(b * HH + h)) * SS + s) * HD + hd]) = o1;
                }
            }
        }
    }
}

// ---------------------------------------------------------------------------
// Per-(b,h) column sums of V -> g_vsum
// ---------------------------------------------------------------------------
__global__ void vsum_kernel(const float* __restrict__ V, float* __restrict__ vs)
{
    __shared__ float red[8][HD];
    const int bh  = blockIdx.x;
    const int col = threadIdx.x & 63;
    const int ch  = threadIdx.x >> 6;          // 0..7
    const float* base = &V[(size_t)bh * SS * HD + (size_t)ch * 256 * HD + col];
    float s = 0.f;
#pragma unroll 8
    for (int k = 0; k < 256; k++) s += base[(size_t)k * HD];
    red[ch][col] = s;
    __syncthreads();
    if (ch == 0) {
        float t = 0.f;
#pragma unroll
        for (int i = 0; i < 8; i++) t += red[i][col];
        vs[bh * HD + col] = t;
    }
}

// ---------------------------------------------------------------------------
// Streaming evidence-attention (flash-style, no max needed), KT=64.
// Q already carries the 1/sqrt(Hd) scale.
// grid: (S/128, B*H), 128 threads; each thread owns one q row.
// ---------------------------------------------------------------------------
__global__ __launch_bounds__(128)
void attn_kernel(const float* __restrict__ Q, const float* __restrict__ K,
                 const float* __restrict__ V, const float* __restrict__ vsum,
                 const float* __restrict__ es_p, const float* __restrict__ eb_p,
                 float* __restrict__ attn_out, float* __restrict__ unc_out)
{
    const int KT = 64;
    __shared__ float Ks[KT][HD];
    __shared__ float Vs[KT][HD];

    const int tid = threadIdx.x;
    const int bh  = blockIdx.y;
    const int q   = blockIdx.x * 128 + tid;

    float4 qr[16];
    {
        const float4* qp = reinterpret_cast<const float4*>(
            &Q[((size_t)bh * SS + q) * HD]);
#pragma unroll
        for (int i = 0; i < 16; i++) qr[i] = qp[i];
    }

    float4 acc[16];
#pragma unroll
    for (int i = 0; i < 16; i++) acc[i] = make_float4(0.f, 0.f, 0.f, 0.f);
    float E = 0.f;

    const float* kbase = &K[(size_t)bh * SS * HD];
    const float* vbase = &V[(size_t)bh * SS * HD];

    for (int k0 = 0; k0 < SS; k0 += KT) {
        __syncthreads();
#pragma unroll
        for (int r = 0; r < 8; r++) {
            int idx  = tid + r * 128;        // 0..1023
            int row  = idx >> 4;             // 0..63
            int quad = idx & 15;
            *reinterpret_cast<float4*>(&Ks[row][quad * 4]) =
                *reinterpret_cast<const float4*>(&kbase[(size_t)(k0 + row) * HD + quad * 4]);
            *reinterpret_cast<float4*>(&Vs[row][quad * 4]) =
                *reinterpret_cast<const float4*>(&vbase[(size_t)(k0 + row) * HD + quad * 4]);
        }
        __syncthreads();

#pragma unroll 4
        for (int kk = 0; kk < KT; kk++) {
            float s = 0.f;
#pragma unroll
            for (int i = 0; i < 16; i++) {
                float4 kv = *reinterpret_cast<const float4*>(&Ks[kk][i * 4]);
                s += qr[i].x * kv.x + qr[i].y * kv.y + qr[i].z * kv.z + qr[i].w * kv.w;
            }
            float p = __expf(s);
            E += p;
#pragma unroll
            for (int i = 0; i < 16; i++) {
                float4 vv = *reinterpret_cast<const float4*>(&Vs[kk][i * 4]);
                acc[i].x += p * vv.x; acc[i].y += p * vv.y;
                acc[i].z += p * vv.z; acc[i].w += p * vv.w;
            }
        }
    }

    const float es  = *es_p;
    const float c   = 1.0f + *eb_p;
    const float den = es * E + c * (float)SS;
    const float inv = 1.0f / den;

    const int b = bh / HH, h = bh % HH;
    const float4* vsv = reinterpret_cast<const float4*>(&vsum[bh * HD]);
    float4* dst = reinterpret_cast<float4*>(
        &attn_out[(((size_t)b * SS + q) * HH + h) * HD]);
#pragma unroll
    for (int i = 0; i < 16; i++) {
        float4 vs4 = vsv[i];
        float4 o;
        o.x = (es * acc[i].x + c * vs4.x) * inv;
        o.y = (es * acc[i].y + c * vs4.y) * inv;
        o.z = (es * acc[i].z + c * vs4.z) * inv;
        o.w = (es * acc[i].w + c * vs4.w) * inv;
        dst[i] = o;
    }
    unc_out[(size_t)bh * SS + q] = (float)SS * inv;
}

// ---------------------------------------------------------------------------
// kernel_launch
// ---------------------------------------------------------------------------
extern "C" void kernel_launch(void* const* d_in, const int* in_sizes, int n_in,
                              void* d_out, int out_size)
{
    const float* x     = (const float*)d_in[0];
    const float* q_w   = (const float*)d_in[1];
    const float* q_b   = (const float*)d_in[2];
    const float* k_w   = (const float*)d_in[3];
    const float* k_b   = (const float*)d_in[4];
    const float* v_w   = (const float*)d_in[5];
    const float* v_b   = (const float*)d_in[6];
    const float* out_w = (const float*)d_in[7];
    const float* out_b = (const float*)d_in[8];
    const float* es    = (const float*)d_in[9];
    const float* eb    = (const float*)d_in[10];
    float* out = (float*)d_out;

    float *Qb, *Kb, *Vb, *Ab, *VS, *Ah, *Al, *Wh, *Wl;
    cudaGetSymbolAddress((void**)&Qb, g_Q);
    cudaGetSymbolAddress((void**)&Kb, g_K);
    cudaGetSymbolAddress((void**)&Vb, g_V);
    cudaGetSymbolAddress((void**)&Ab, g_attn);
    cudaGetSymbolAddress((void**)&VS, g_vsum);
    cudaGetSymbolAddress((void**)&Ah, g_Ah);
    cudaGetSymbolAddress((void**)&Al, g_Al);
    cudaGetSymbolAddress((void**)&Wh, g_Wh);
    cudaGetSymbolAddress((void**)&Wl, g_Wl);

    const float inv_sqrt_hd = 0.125f;   // 1/sqrt(64), folded into Q after bias

    const int nX4 = MM * DD / 4;        // 1M float4
    const int nW4 = DD * DD / 4;        // 256K float4
    dim3 gemm_grid(DD / 128, MM / 128); // (8, 32)

    // x split once, reused by the 3 projections
    split_kernel<<<(nX4 + 255) / 256, 256>>>(x, Ah, Al, nX4);

    split_kernel<<<(nW4 + 255) / 256, 256>>>(q_w, Wh, Wl, nW4);
    gemm_split<1><<<gemm_grid, 256>>>(Ah, Al, Wh, Wl, q_b, Qb, inv_sqrt_hd);

    split_kernel<<<(nW4 + 255) / 256, 256>>>(k_w, Wh, Wl, nW4);
    gemm_split<1><<<gemm_grid, 256>>>(Ah, Al, Wh, Wl, k_b, Kb, 1.0f);

    split_kernel<<<(nW4 + 255) / 256, 256>>>(v_w, Wh, Wl, nW4);
    gemm_split<1><<<gemm_grid, 256>>>(Ah, Al, Wh, Wl, v_b, Vb, 1.0f);

    vsum_kernel<<<BB * HH, 512>>>(Vb, VS);

    dim3 attn_grid(SS / 128, BB * HH);  // (16, 32)
    attn_kernel<<<attn_grid, 128>>>(Qb, Kb, Vb, VS, es, eb,
                                    Ab, out + (size_t)BB * SS * DD);

    // out-projection: split attn output (reuse A buffers) + out_w
    split_kernel<<<(nX4 + 255) / 256, 256>>>(Ab, Ah, Al, nX4);
    split_kernel<<<(nW4 + 255) / 256, 256>>>(out_w, Wh, Wl, nW4);
    gemm_split<0><<<gemm_grid, 256>>>(Ah, Al, Wh, Wl, out_b, out, 1.0f);
}